// round 9
// baseline (speedup 1.0000x reference)
#include <cuda_runtime.h>
#include <math.h>

// RoIPool (max) — features (2,256,50,76) f32, rois (128,5) f32 -> out (128,256,7,7) f32
// Bin arithmetic matches the XLA-lowered JAX reference bit-for-bit (x/7 lowered to
// x * fp32(1/7)).
// R8 structure (warp-per-(roi,channel), row-coalesced):
//   - block = (roi, cgroup of 8); warp = one (roi, channel)
//   - per row h of the roi window: ONE coalesced LDG loads the whole w-window
//     (<= ~21 cells <= 32 lanes, 1-2 cache lines)
//   - 7 w-bin maxes via 4 predicated dynamic shuffles (bin width <= 4)
//   - 49 outputs live in 2 regs/lane; per row, each output pulls its pw rowmax via
//     shuffle and accumulates if h is inside its h-bin (uniform predicates)
//   - coalesced 49-float contiguous write per warp
//   - generic fallback if w-window > 32 or any w-bin > 4 (not expected; seed-robust)

#define C_      256
#define H_      50
#define W_      76
#define PLANE_  (H_ * W_)
#define PH_     7
#define PW_     7
#define BINS_   (PH_ * PW_)      // 49
#define NROIS_  128
#define SCALE_  0.0625f
// fp32 nearest to 1/7 (0x3E124925)
#define RECIP7_ 0.14285714924335479736328125f
#define NEG_    (-3.402823466e+38f)
#define CPB_    8                // channels (warps) per block
#define TPB_    (CPB_ * 32)

__global__ __launch_bounds__(TPB_)
void roipool_kernel(const float* __restrict__ feat,
                    const float* __restrict__ rois,
                    float* __restrict__ out)
{
    const int roi  = blockIdx.x;
    const int tid  = threadIdx.x;
    const int wid  = tid >> 5;
    const int lane = tid & 31;
    const int c    = blockIdx.y * CPB_ + wid;

    __shared__ int2 s_h[PH_];    // {hstart, hend}
    __shared__ int2 s_w[PW_];    // {wstart, wend}
    __shared__ int  s_b;         // batch
    __shared__ int  s_fb;        // fallback flag

    // ---- per-block roi decode (bit-exact XLA arithmetic) ----
    if (tid < 14) {
        const float* r = rois + roi * 5;
        if (tid < PH_) {
            const int y1 = (int)rintf(__fmul_rn(r[2], SCALE_));
            const int y2 = (int)rintf(__fmul_rn(r[4], SCALE_));
            const float bh = __fmul_rn((float)max(y2 - y1 + 1, 1), RECIP7_);
            int hs = (int)floorf(__fmul_rn((float)tid,       bh)) + y1;
            int he = (int)ceilf (__fmul_rn((float)(tid + 1), bh)) + y1;
            s_h[tid] = make_int2(min(max(hs, 0), H_), min(max(he, 0), H_));
            if (tid == 0) s_b = (int)r[0];
        } else {
            const int p  = tid - PH_;
            const int x1 = (int)rintf(__fmul_rn(r[1], SCALE_));
            const int x2 = (int)rintf(__fmul_rn(r[3], SCALE_));
            const float bw = __fmul_rn((float)max(x2 - x1 + 1, 1), RECIP7_);
            int ws = (int)floorf(__fmul_rn((float)p,       bw)) + x1;
            int we = (int)ceilf (__fmul_rn((float)(p + 1), bw)) + x1;
            s_w[p] = make_int2(min(max(ws, 0), W_), min(max(we, 0), W_));
        }
    }
    __syncthreads();
    if (tid == 0) {
        int fb = (s_w[PW_ - 1].y - s_w[0].x) > 32;
        #pragma unroll
        for (int p = 0; p < PW_; ++p)
            fb |= (s_w[p].y - s_w[p].x) > 4;
        s_fb = fb;
    }
    __syncthreads();

    const float* plane = feat + ((size_t)s_b * C_ + c) * PLANE_;
    const size_t obase = ((size_t)roi * C_ + c) * BINS_;

    // per-lane outputs: o1 = lane (0..31), o2 = lane+32 (valid if < 49)
    const int o1 = lane, o2 = lane + 32;
    const int ph1 = o1 / PW_, pw1 = o1 - ph1 * PW_;
    const int ph2 = o2 / PW_, pw2 = o2 - ph2 * PW_;
    const bool v2 = (o2 < BINS_);

    const int hs1 = s_h[ph1].x, he1 = s_h[ph1].y;
    const int hs2 = v2 ? s_h[ph2].x : 0;
    const int he2 = v2 ? s_h[ph2].y : -1;       // pred never true if invalid

    float a1 = NEG_, a2 = NEG_;

    if (!s_fb) {
        const int wbase  = s_w[0].x;
        const int nwidth = s_w[PW_ - 1].y - wbase;

        // per-lane w-gather params (lanes 0..6 produce the 7 rowmaxes)
        int wsrel = 0, nbin = 0;
        if (lane < PW_) {
            wsrel = s_w[lane].x - wbase;
            nbin  = s_w[lane].y - s_w[lane].x;
        }

        const int h0 = s_h[0].x, h1 = s_h[PH_ - 1].y;
        const float* rowp = plane + h0 * W_ + wbase;

        for (int h = h0; h < h1; ++h, rowp += W_) {
            // one coalesced row load of the whole window
            float v = (lane < nwidth) ? __ldg(rowp + lane) : NEG_;

            // rowmax per pw (valid in lanes 0..6)
            float rm = NEG_;
            #pragma unroll
            for (int k = 0; k < 4; ++k) {
                const float t = __shfl_sync(0xffffffffu, v, wsrel + k);
                if (k < nbin) rm = fmaxf(rm, t);
            }

            // distribute rowmax to output accumulators
            const float r1 = __shfl_sync(0xffffffffu, rm, pw1);
            const float r2 = __shfl_sync(0xffffffffu, rm, pw2);
            if (h >= hs1 && h < he1) a1 = fmaxf(a1, r1);
            if (h >= hs2 && h < he2) a2 = fmaxf(a2, r2);
        }
    } else {
        // Seed-robust generic fallback: direct global gather per output.
        {
            const int ws = s_w[pw1].x, we = s_w[pw1].y;
            for (int h = hs1; h < he1; ++h)
                for (int w = ws; w < we; ++w)
                    a1 = fmaxf(a1, __ldg(plane + h * W_ + w));
        }
        if (v2) {
            const int ws = s_w[pw2].x, we = s_w[pw2].y;
            for (int h = hs2; h < he2; ++h)
                for (int w = ws; w < we; ++w)
                    a2 = fmaxf(a2, __ldg(plane + h * W_ + w));
        }
    }

    // empty bins stayed at NEG_ -> 0 (randn data never equals -FLT_MAX)
    out[obase + o1] = (a1 == NEG_) ? 0.0f : a1;
    if (v2) out[obase + o2] = (a2 == NEG_) ? 0.0f : a2;
}

extern "C" void kernel_launch(void* const* d_in, const int* in_sizes, int n_in,
                              void* d_out, int out_size)
{
    // Autodetect input order by element count (rois = 640 elems, features = 1,945,600).
    const float* feat;
    const float* rois;
    if (in_sizes[0] == NROIS_ * 5) {
        rois = (const float*)d_in[0];
        feat = (const float*)d_in[1];
    } else {
        feat = (const float*)d_in[0];
        rois = (const float*)d_in[1];
    }
    float* out = (float*)d_out;

    dim3 block(TPB_);
    dim3 grid(NROIS_, C_ / CPB_);    // 128 rois x 32 channel-groups; warp=(roi,c)
    roipool_kernel<<<grid, block>>>(feat, rois, out);
}

// round 10
// speedup vs baseline: 1.3433x; 1.3433x over previous
#include <cuda_runtime.h>
#include <math.h>

// RoIPool (max) — features (2,256,50,76) f32, rois (128,5) f32 -> out (128,256,7,7) f32
// Bin arithmetic matches the XLA-lowered JAX reference bit-for-bit (x/7 lowered to
// x * fp32(1/7)).
// R9 structure (separable max, column-major, warp = (roi, channel)):
//   lane = w-offset within the roi window (window <= 32 wide for this dist)
//   Phase 1: per-lane h-reduction per h-bin -> 7 column maxes; every LDG is a
//            fully-coalesced window row (1-2 cache lines) -> ~2x fewer L1tex
//            wavefronts than the scattered per-output gather (the measured bound).
//   Phase 2: per ph, 4 predicated shuffles gather the <=4 column maxes of each
//            w-bin (shuffles amortized over window height, unlike R8).
//   Fallback: generic per-output gather if window > 32 / bin > 4 / bh > 3.

#define C_      256
#define H_      50
#define W_      76
#define PLANE_  (H_ * W_)
#define PH_     7
#define PW_     7
#define BINS_   (PH_ * PW_)
#define NROIS_  128
#define SCALE_  0.0625f
// fp32 nearest to 1/7 (0x3E124925)
#define RECIP7_ 0.14285714924335479736328125f
#define NEG_    (-3.402823466e+38f)
#define WPB_    8                 // warps (channels) per block
#define TPB_    (WPB_ * 32)

template<int NH>
__device__ __forceinline__ void colmax_phase(float cm[PH_],
                                             const float* __restrict__ colp,
                                             bool act, const int2* __restrict__ sh)
{
    #pragma unroll
    for (int ph = 0; ph < PH_; ++ph) {
        const int hs = sh[ph].x;
        const int nh = sh[ph].y - hs;
        const float* p = colp + hs * W_;
        float m = NEG_;
        #pragma unroll
        for (int i = 0; i < NH; ++i) {
            if (act && i < nh)
                m = fmaxf(m, __ldg(p + i * W_));
        }
        cm[ph] = m;
    }
}

__global__ __launch_bounds__(TPB_)
void roipool_kernel(const float* __restrict__ feat,
                    const float* __restrict__ rois,
                    float* __restrict__ out)
{
    const int roi  = blockIdx.x;
    const int tid  = threadIdx.x;
    const int wid  = tid >> 5;
    const int lane = tid & 31;
    const int c    = blockIdx.y * WPB_ + wid;

    __shared__ int2 s_h[PH_];     // {hstart, hend}
    __shared__ int2 s_w[PW_];     // {wstart, wend}
    __shared__ int  s_b;          // batch index
    __shared__ int  s_th;         // h-tier (2/3/4), 0 = fallback
    __shared__ int  s_fb;         // fallback flag

    // ---- per-block roi decode (bit-exact XLA arithmetic) ----
    if (tid < 14) {
        const float* r = rois + roi * 5;
        if (tid < PH_) {
            const int y1 = (int)rintf(__fmul_rn(r[2], SCALE_));
            const int y2 = (int)rintf(__fmul_rn(r[4], SCALE_));
            const float bh = __fmul_rn((float)max(y2 - y1 + 1, 1), RECIP7_);
            int hs = (int)floorf(__fmul_rn((float)tid,       bh)) + y1;
            int he = (int)ceilf (__fmul_rn((float)(tid + 1), bh)) + y1;
            s_h[tid] = make_int2(min(max(hs, 0), H_), min(max(he, 0), H_));
            if (tid == 0) {
                s_b  = (int)r[0];
                s_th = (bh <= 1.0f) ? 2 : (bh <= 2.0f) ? 3 : (bh <= 3.0f) ? 4 : 0;
            }
        } else {
            const int p  = tid - PH_;
            const int x1 = (int)rintf(__fmul_rn(r[1], SCALE_));
            const int x2 = (int)rintf(__fmul_rn(r[3], SCALE_));
            const float bw = __fmul_rn((float)max(x2 - x1 + 1, 1), RECIP7_);
            int ws = (int)floorf(__fmul_rn((float)p,       bw)) + x1;
            int we = (int)ceilf (__fmul_rn((float)(p + 1), bw)) + x1;
            s_w[p] = make_int2(min(max(ws, 0), W_), min(max(we, 0), W_));
        }
    }
    __syncthreads();
    if (tid == 0) {
        int fb = (s_th == 0) || ((s_w[PW_ - 1].y - s_w[0].x) > 32);
        #pragma unroll
        for (int p = 0; p < PW_; ++p)
            fb |= (s_w[p].y - s_w[p].x) > 4;
        s_fb = fb;
    }
    __syncthreads();

    const float* plane = feat + ((size_t)s_b * C_ + c) * PLANE_;
    const size_t obase = ((size_t)roi * C_ + c) * BINS_;

    if (!s_fb) {
        const int wbase  = s_w[0].x;
        const int nwidth = s_w[PW_ - 1].y - wbase;
        const bool act   = (lane < nwidth);
        const float* colp = plane + wbase + lane;

        // Phase 1: 7 per-column h-bin maxes (coalesced row loads)
        float cm[PH_];
        const int th = s_th;
        if      (th == 2) colmax_phase<2>(cm, colp, act, s_h);
        else if (th == 3) colmax_phase<3>(cm, colp, act, s_h);
        else              colmax_phase<4>(cm, colp, act, s_h);

        // Phase 2: per-lane (pw = lane < 7) w-bin gather params
        int wsrel = 0, nbin = 0;
        if (lane < PW_) {
            wsrel = s_w[lane].x - wbase;
            nbin  = s_w[lane].y - s_w[lane].x;
        }

        #pragma unroll
        for (int ph = 0; ph < PH_; ++ph) {
            const float v = cm[ph];
            float m = NEG_;
            #pragma unroll
            for (int k = 0; k < 4; ++k) {
                const float t = __shfl_sync(0xffffffffu, v, wsrel + k);
                if (k < nbin) m = fmaxf(m, t);
            }
            if (lane < PW_)
                out[obase + ph * PW_ + lane] = (m == NEG_) ? 0.0f : m;
        }
    } else {
        // Seed-robust generic fallback: per-output gather, warp covers 49 bins.
        for (int o = lane; o < BINS_; o += 32) {
            const int ph = o / PW_;
            const int pw = o - ph * PW_;
            const int2 hb = s_h[ph];
            const int2 wb = s_w[pw];
            float m = NEG_;
            for (int h = hb.x; h < hb.y; ++h)
                for (int w = wb.x; w < wb.y; ++w)
                    m = fmaxf(m, __ldg(plane + h * W_ + w));
            out[obase + o] = (m == NEG_) ? 0.0f : m;
        }
    }
}

extern "C" void kernel_launch(void* const* d_in, const int* in_sizes, int n_in,
                              void* d_out, int out_size)
{
    // Autodetect input order by element count (rois = 640 elems, features = 1,945,600).
    const float* feat;
    const float* rois;
    if (in_sizes[0] == NROIS_ * 5) {
        rois = (const float*)d_in[0];
        feat = (const float*)d_in[1];
    } else {
        feat = (const float*)d_in[0];
        rois = (const float*)d_in[1];
    }
    float* out = (float*)d_out;

    dim3 block(TPB_);
    dim3 grid(NROIS_, C_ / WPB_);    // 128 rois x 32 channel-groups; warp = (roi, c)
    roipool_kernel<<<grid, block>>>(feat, rois, out);
}